// round 5
// baseline (speedup 1.0000x reference)
#include <cuda_runtime.h>
#include <cstdint>
#include <math.h>

#define D_MODEL  2048
#define N_HEADS  16
#define HEAD_DIM 128
#define BATCH    2
#define SEQ      2048
#define NTOK     (BATCH * SEQ)

__device__ float g_q [NTOK * D_MODEL];
__device__ float g_k [NTOK * HEAD_DIM];
__device__ float g_v [NTOK * HEAD_DIM];
__device__ float g_ao[NTOK * D_MODEL];

// ---------------------------------------------------------------------------
// Helpers
// ---------------------------------------------------------------------------
__device__ __forceinline__ uint32_t f2tf32(float x) {
    uint32_t r;
    asm("cvt.rna.tf32.f32 %0, %1;" : "=r"(r) : "f"(x));
    return r;
}

__device__ __forceinline__ void mma_tf32(float* d,
    uint32_t a0, uint32_t a1, uint32_t a2, uint32_t a3,
    uint32_t b0, uint32_t b1)
{
    asm volatile(
        "mma.sync.aligned.m16n8k8.row.col.f32.tf32.tf32.f32 "
        "{%0,%1,%2,%3},{%4,%5,%6,%7},{%8,%9},{%0,%1,%2,%3};"
        : "+f"(d[0]), "+f"(d[1]), "+f"(d[2]), "+f"(d[3])
        : "r"(a0), "r"(a1), "r"(a2), "r"(a3), "r"(b0), "r"(b1));
}

__device__ __forceinline__ void cp_async16(uint32_t dst_smem, const void* src) {
    asm volatile("cp.async.cg.shared.global [%0], [%1], 16;"
                 :: "r"(dst_smem), "l"(src));
}
__device__ __forceinline__ void cp_commit() {
    asm volatile("cp.async.commit_group;");
}
__device__ __forceinline__ void cp_wait_all() {
    asm volatile("cp.async.wait_group 0;" ::: "memory");
}

// ---------------------------------------------------------------------------
// TF32 GEMM v2: 128x128x32 tile, 8 warps @64x32, double-buffered (dynamic smem).
// A: LDG -> reg -> k-permuted STS (tf32).  Fragment pairs via LDS.64.
//    phys(k) = (k>>3)*8 + ((k>>2)&1) + 2*(k&3)
// B: cp.async raw fp32, cvt after LDS.
// ---------------------------------------------------------------------------
#define GBM 128
#define GBN 128
#define GBK 32
#define ASTR 40
#define BSTR 136
// dynamic smem layout: As[2][GBM*ASTR] u32, then Bs[2][GBK*BSTR] float
#define GEMM_SMEM_BYTES ((2 * GBM * ASTR + 2 * GBK * BSTR) * 4)

__global__ __launch_bounds__(256, 2) void tf32_gemm_bias(
    int M, int N, int K,
    const float* __restrict__ A,
    const float* __restrict__ B,
    const float* __restrict__ bias,
    float* __restrict__ C)
{
    extern __shared__ uint32_t gsm[];
    uint32_t* As0 = gsm;
    uint32_t* As1 = gsm + GBM * ASTR;
    float*    Bs0 = (float*)(gsm + 2 * GBM * ASTR);
    float*    Bs1 = Bs0 + GBK * BSTR;

    const int tid  = threadIdx.x;
    const int wid  = tid >> 5;
    const int lane = tid & 31;
    const int g    = lane >> 2;
    const int t4   = lane & 3;
    const int wm   = (wid >> 2) * 64;
    const int wn   = (wid & 3) * 32;

    const float* Ab = A + (size_t)blockIdx.y * GBM * K;
    const float* Bb = B + (size_t)blockIdx.x * GBN;

    const int arow  = tid >> 3;
    const int acol  = (tid & 7) * 4;
    const int abase = (acol >> 3) * 8 + ((acol >> 2) & 1);   // + 2*j

    float acc[4][4][4];
#pragma unroll
    for (int mi = 0; mi < 4; mi++)
#pragma unroll
        for (int ni = 0; ni < 4; ni++)
#pragma unroll
            for (int r = 0; r < 4; r++) acc[mi][ni][r] = 0.0f;

    float4 rA[4];

    // ---- prologue: tile 0 ----
#pragma unroll
    for (int q = 0; q < 4; q++) {
        int id = tid + 256 * q;
        int brow = id >> 5, bcol = (id & 31) * 4;
        cp_async16((uint32_t)__cvta_generic_to_shared(&Bs0[brow * BSTR + bcol]),
                   &Bb[(size_t)brow * N + bcol]);
    }
    cp_commit();
#pragma unroll
    for (int i = 0; i < 4; i++)
        rA[i] = *(const float4*)&Ab[(size_t)(arow + 32 * i) * K + acol];
#pragma unroll
    for (int i = 0; i < 4; i++) {
        uint32_t* dst = &As0[(arow + 32 * i) * ASTR + abase];
        dst[0] = f2tf32(rA[i].x);
        dst[2] = f2tf32(rA[i].y);
        dst[4] = f2tf32(rA[i].z);
        dst[6] = f2tf32(rA[i].w);
    }
    cp_wait_all();
    __syncthreads();

    const int T = K / GBK;
    for (int t = 0; t < T; t++) {
        uint32_t* Asc = (t & 1) ? As1 : As0;
        uint32_t* Asn = (t & 1) ? As0 : As1;
        float*    Bsc = (t & 1) ? Bs1 : Bs0;
        float*    Bsn = (t & 1) ? Bs0 : Bs1;

        if (t + 1 < T) {
            const int k0n = (t + 1) * GBK;
#pragma unroll
            for (int q = 0; q < 4; q++) {
                int id = tid + 256 * q;
                int brow = id >> 5, bcol = (id & 31) * 4;
                cp_async16((uint32_t)__cvta_generic_to_shared(&Bsn[brow * BSTR + bcol]),
                           &Bb[(size_t)(k0n + brow) * N + bcol]);
            }
            cp_commit();
#pragma unroll
            for (int i = 0; i < 4; i++)
                rA[i] = *(const float4*)&Ab[(size_t)(arow + 32 * i) * K + k0n + acol];
        }

        // ---- compute current stage ----
#pragma unroll
        for (int ks = 0; ks < 4; ks++) {
            uint2 ap[4][2];
#pragma unroll
            for (int mi = 0; mi < 4; mi++) {
                const int r0 = wm + mi * 16 + g;
                ap[mi][0] = *(const uint2*)&Asc[(r0    ) * ASTR + ks * 8 + 2 * t4];
                ap[mi][1] = *(const uint2*)&Asc[(r0 + 8) * ASTR + ks * 8 + 2 * t4];
            }
#pragma unroll
            for (int ni = 0; ni < 4; ni++) {
                const int c0 = wn + ni * 8 + g;
                uint32_t b0 = f2tf32(Bsc[(ks * 8 + t4    ) * BSTR + c0]);
                uint32_t b1 = f2tf32(Bsc[(ks * 8 + t4 + 4) * BSTR + c0]);
#pragma unroll
                for (int mi = 0; mi < 4; mi++)
                    mma_tf32(acc[mi][ni],
                             ap[mi][0].x, ap[mi][1].x, ap[mi][0].y, ap[mi][1].y,
                             b0, b1);
            }
        }

        if (t + 1 < T) {
#pragma unroll
            for (int i = 0; i < 4; i++) {
                uint32_t* dst = &Asn[(arow + 32 * i) * ASTR + abase];
                dst[0] = f2tf32(rA[i].x);
                dst[2] = f2tf32(rA[i].y);
                dst[4] = f2tf32(rA[i].z);
                dst[6] = f2tf32(rA[i].w);
            }
            cp_wait_all();
        }
        __syncthreads();
    }

    const int rowBase = blockIdx.y * GBM + wm;
    const int colBase = blockIdx.x * GBN + wn;
#pragma unroll
    for (int mi = 0; mi < 4; mi++) {
#pragma unroll
        for (int ni = 0; ni < 4; ni++) {
            const int col = colBase + ni * 8 + 2 * t4;
            const int r0  = rowBase + mi * 16 + g;
            float2 v0, v1;
            v0.x = acc[mi][ni][0] + bias[col];
            v0.y = acc[mi][ni][1] + bias[col + 1];
            v1.x = acc[mi][ni][2] + bias[col];
            v1.y = acc[mi][ni][3] + bias[col + 1];
            *(float2*)&C[(size_t)r0 * N + col]       = v0;
            *(float2*)&C[(size_t)(r0 + 8) * N + col] = v1;
        }
    }
}

// ---------------------------------------------------------------------------
// Fused K/V projection (fp32), unchanged.
// ---------------------------------------------------------------------------
__global__ __launch_bounds__(128) void kv_proj_kernel(
    const float* __restrict__ x,
    const float* __restrict__ Wk, const float* __restrict__ bk,
    const float* __restrict__ Wv, const float* __restrict__ bv,
    float* __restrict__ Kout, float* __restrict__ Vout)
{
    const float* W    = blockIdx.x ? Wv : Wk;
    const float* bias = blockIdx.x ? bv : bk;
    float*       out  = blockIdx.x ? Vout : Kout;

    __shared__ float As_[16][68];
    __shared__ float Bs_[16][128];

    const int tid = threadIdx.x;
    const int tr  = tid / 16;
    const int tc  = tid % 16;

    float acc[8][8];
#pragma unroll
    for (int i = 0; i < 8; i++)
#pragma unroll
        for (int j = 0; j < 8; j++) acc[i][j] = 0.0f;

    const float* Ab = x + (size_t)blockIdx.y * 64 * D_MODEL;
    const int ar = tid >> 2;
    const int ac = (tid & 3) * 4;
    const int br = tid >> 5;
    const int bc = (tid & 31) * 4;

    for (int k0 = 0; k0 < D_MODEL; k0 += 16) {
#pragma unroll
        for (int rr = 0; rr < 2; rr++) {
            int row = ar + rr * 32;
            float4 a = *(const float4*)&Ab[(size_t)row * D_MODEL + k0 + ac];
            As_[ac + 0][row] = a.x;
            As_[ac + 1][row] = a.y;
            As_[ac + 2][row] = a.z;
            As_[ac + 3][row] = a.w;
        }
#pragma unroll
        for (int rr = 0; rr < 4; rr++) {
            int row = br + rr * 4;
            *(float4*)&Bs_[row][bc] =
                *(const float4*)&W[(size_t)(k0 + row) * HEAD_DIM + bc];
        }
        __syncthreads();

#pragma unroll
        for (int kk = 0; kk < 16; kk++) {
            float regM[8], regN[8];
#pragma unroll
            for (int i = 0; i < 8; i++) regM[i] = As_[kk][tr * 8 + i];
#pragma unroll
            for (int j = 0; j < 8; j++) regN[j] = Bs_[kk][tc * 8 + j];
#pragma unroll
            for (int i = 0; i < 8; i++)
#pragma unroll
                for (int j = 0; j < 8; j++)
                    acc[i][j] += regM[i] * regN[j];
        }
        __syncthreads();
    }

    const int rowBase = blockIdx.y * 64 + tr * 8;
    const int colBase = tc * 8;
#pragma unroll
    for (int i = 0; i < 8; i++) {
#pragma unroll
        for (int j = 0; j < 8; j += 4) {
            float4 t;
            t.x = acc[i][j + 0] + bias[colBase + j + 0];
            t.y = acc[i][j + 1] + bias[colBase + j + 1];
            t.z = acc[i][j + 2] + bias[colBase + j + 2];
            t.w = acc[i][j + 3] + bias[colBase + j + 3];
            *(float4*)&out[(size_t)(rowBase + i) * HEAD_DIM + colBase + j] = t;
        }
    }
}

// ---------------------------------------------------------------------------
// TF32 MMA flash attention v2. BQ=128, BKT=64, 8 warps.
// Q/K stored k-permuted (LDS.64 fragments in score loop). V plain (STS.128).
// ---------------------------------------------------------------------------
#define AQ 128
#define AK 64
#define QP 136
#define KP 136
#define VP 136

__global__ __launch_bounds__(256) void mqa_attn_tf32(
    const float* __restrict__ Q,
    const float* __restrict__ Kg,
    const float* __restrict__ Vg,
    const int* __restrict__ mask,
    float* __restrict__ Og)
{
    extern __shared__ uint32_t sm_u[];
    uint32_t* Qs   = sm_u;                 // AQ x QP (k-permuted tf32)
    uint32_t* Ks   = Qs + AQ * QP;         // AK x KP (k-permuted tf32)
    uint32_t* Vs   = Ks + AK * KP;         // AK x VP (plain tf32)
    float*   sbias = (float*)(Vs + AK * VP);  // AK

    const int tid  = threadIdx.x;
    const int wid  = tid >> 5;
    const int lane = tid & 31;
    const int g    = lane >> 2;
    const int t4   = lane & 3;
    const int b  = blockIdx.z, h = blockIdx.y;
    const int q0 = blockIdx.x * AQ;
    const int wrow = wid * 16;

    // Load Q tile (k-permuted tf32)
    const float* Qp = Q + ((size_t)(b * SEQ + q0)) * D_MODEL + h * HEAD_DIM;
    for (int i = tid; i < AQ * HEAD_DIM / 4; i += 256) {
        int r = i >> 5, c = (i & 31) << 2;
        float4 qv = *(const float4*)&Qp[(size_t)r * D_MODEL + c];
        uint32_t* dst = &Qs[r * QP + (c >> 3) * 8 + ((c >> 2) & 1)];
        dst[0] = f2tf32(qv.x);
        dst[2] = f2tf32(qv.y);
        dst[4] = f2tf32(qv.z);
        dst[6] = f2tf32(qv.w);
    }

    float m0 = -1e30f, m1 = -1e30f, l0 = 0.0f, l1 = 0.0f;
    float o[16][4];
#pragma unroll
    for (int n = 0; n < 16; n++)
#pragma unroll
        for (int r = 0; r < 4; r++) o[n][r] = 0.0f;

    const float scale = 0.08838834764831845f;

    for (int k0 = 0; k0 < SEQ; k0 += AK) {
        __syncthreads();
        const float* Kp = Kg + ((size_t)(b * SEQ + k0)) * HEAD_DIM;
        const float* Vp = Vg + ((size_t)(b * SEQ + k0)) * HEAD_DIM;
        for (int i = tid; i < AK * HEAD_DIM / 4; i += 256) {
            int r = i >> 5, c = (i & 31) << 2;
            float4 kv = *(const float4*)&Kp[(size_t)r * HEAD_DIM + c];
            uint32_t* kd = &Ks[r * KP + (c >> 3) * 8 + ((c >> 2) & 1)];
            kd[0] = f2tf32(kv.x);
            kd[2] = f2tf32(kv.y);
            kd[4] = f2tf32(kv.z);
            kd[6] = f2tf32(kv.w);
            float4 vv = *(const float4*)&Vp[(size_t)r * HEAD_DIM + c];
            uint4 vu = make_uint4(f2tf32(vv.x), f2tf32(vv.y),
                                  f2tf32(vv.z), f2tf32(vv.w));
            *(uint4*)&Vs[r * VP + c] = vu;
        }
        if (tid < AK)
            sbias[tid] = mask[(size_t)b * SEQ + k0 + tid] ? 0.0f : -1e9f;
        __syncthreads();

        // ---- Scores: S = Q @ K^T (LDS.64 fragments) ----
        float s[8][4];
#pragma unroll
        for (int j = 0; j < 8; j++)
#pragma unroll
            for (int r = 0; r < 4; r++) s[j][r] = 0.0f;

#pragma unroll
        for (int ks = 0; ks < 16; ks++) {
            uint2 aq0 = *(const uint2*)&Qs[(wrow + g    ) * QP + ks * 8 + 2 * t4];
            uint2 aq1 = *(const uint2*)&Qs[(wrow + g + 8) * QP + ks * 8 + 2 * t4];
#pragma unroll
            for (int j = 0; j < 8; j++) {
                uint2 bp = *(const uint2*)&Ks[(j * 8 + g) * KP + ks * 8 + 2 * t4];
                mma_tf32(s[j], aq0.x, aq1.x, aq0.y, aq1.y, bp.x, bp.y);
            }
        }

        // ---- scale + mask, row max ----
        float rmax0 = -1e30f, rmax1 = -1e30f;
#pragma unroll
        for (int j = 0; j < 8; j++) {
            float2 sb = *(float2*)&sbias[j * 8 + 2 * t4];
            s[j][0] = s[j][0] * scale + sb.x;
            s[j][1] = s[j][1] * scale + sb.y;
            s[j][2] = s[j][2] * scale + sb.x;
            s[j][3] = s[j][3] * scale + sb.y;
            rmax0 = fmaxf(rmax0, fmaxf(s[j][0], s[j][1]));
            rmax1 = fmaxf(rmax1, fmaxf(s[j][2], s[j][3]));
        }
#pragma unroll
        for (int off = 1; off <= 2; off <<= 1) {
            rmax0 = fmaxf(rmax0, __shfl_xor_sync(0xffffffffu, rmax0, off));
            rmax1 = fmaxf(rmax1, __shfl_xor_sync(0xffffffffu, rmax1, off));
        }
        const float mn0 = fmaxf(m0, rmax0);
        const float mn1 = fmaxf(m1, rmax1);
        const float c0 = __expf(m0 - mn0);
        const float c1 = __expf(m1 - mn1);
        m0 = mn0; m1 = mn1;

        float rs0 = 0.0f, rs1 = 0.0f;
        uint32_t pt[8][4];
#pragma unroll
        for (int j = 0; j < 8; j++) {
            float p0 = __expf(s[j][0] - mn0);
            float p1 = __expf(s[j][1] - mn0);
            float p2 = __expf(s[j][2] - mn1);
            float p3 = __expf(s[j][3] - mn1);
            rs0 += p0 + p1;
            rs1 += p2 + p3;
            pt[j][0] = f2tf32(p0);
            pt[j][1] = f2tf32(p1);
            pt[j][2] = f2tf32(p2);
            pt[j][3] = f2tf32(p3);
        }
#pragma unroll
        for (int off = 1; off <= 2; off <<= 1) {
            rs0 += __shfl_xor_sync(0xffffffffu, rs0, off);
            rs1 += __shfl_xor_sync(0xffffffffu, rs1, off);
        }
        l0 = l0 * c0 + rs0;
        l1 = l1 * c1 + rs1;

#pragma unroll
        for (int n = 0; n < 16; n++) {
            o[n][0] *= c0; o[n][1] *= c0;
            o[n][2] *= c1; o[n][3] *= c1;
        }

        // ---- O += P @ V (A-frags from pt via shuffles) ----
        const int src1 = (g << 2) + (t4 >> 1);
        const int src2 = src1 + 2;
        const bool odd = (t4 & 1);
#pragma unroll
        for (int j = 0; j < 8; j++) {
            uint32_t x00 = __shfl_sync(0xffffffffu, pt[j][0], src1);
            uint32_t x01 = __shfl_sync(0xffffffffu, pt[j][1], src1);
            uint32_t x10 = __shfl_sync(0xffffffffu, pt[j][0], src2);
            uint32_t x11 = __shfl_sync(0xffffffffu, pt[j][1], src2);
            uint32_t x20 = __shfl_sync(0xffffffffu, pt[j][2], src1);
            uint32_t x21 = __shfl_sync(0xffffffffu, pt[j][3], src1);
            uint32_t x30 = __shfl_sync(0xffffffffu, pt[j][2], src2);
            uint32_t x31 = __shfl_sync(0xffffffffu, pt[j][3], src2);
            uint32_t a0 = odd ? x01 : x00;
            uint32_t a2 = odd ? x11 : x10;
            uint32_t a1 = odd ? x21 : x20;
            uint32_t a3 = odd ? x31 : x30;
#pragma unroll
            for (int n = 0; n < 16; n++) {
                uint32_t b0 = Vs[(j * 8 + t4    ) * VP + n * 8 + g];
                uint32_t b1 = Vs[(j * 8 + t4 + 4) * VP + n * 8 + g];
                mma_tf32(o[n], a0, a1, a2, a3, b0, b1);
            }
        }
    }

    // ---- Epilogue ----
    const float inv0 = 1.0f / l0;
    const float inv1 = 1.0f / l1;
    float* Op0 = Og + ((size_t)(b * SEQ + q0 + wrow + g    )) * D_MODEL + h * HEAD_DIM;
    float* Op1 = Og + ((size_t)(b * SEQ + q0 + wrow + g + 8)) * D_MODEL + h * HEAD_DIM;
#pragma unroll
    for (int n = 0; n < 16; n++) {
        const int col = n * 8 + 2 * t4;
        float2 v0, v1;
        v0.x = o[n][0] * inv0; v0.y = o[n][1] * inv0;
        v1.x = o[n][2] * inv1; v1.y = o[n][3] * inv1;
        *(float2*)&Op0[col] = v0;
        *(float2*)&Op1[col] = v1;
    }
}

// ---------------------------------------------------------------------------
extern "C" void kernel_launch(void* const* d_in, const int* in_sizes, int n_in,
                              void* d_out, int out_size)
{
    const float* x    = (const float*)d_in[0];
    const int*   mask = (const int*)d_in[1];
    const float* Wq   = (const float*)d_in[2];
    const float* bq   = (const float*)d_in[3];
    const float* Wk   = (const float*)d_in[4];
    const float* bk   = (const float*)d_in[5];
    const float* Wv   = (const float*)d_in[6];
    const float* bv   = (const float*)d_in[7];
    const float* Wo   = (const float*)d_in[8];
    const float* bo   = (const float*)d_in[9];
    float* out = (float*)d_out;

    float *q, *k, *v, *ao;
    cudaGetSymbolAddress((void**)&q,  g_q);
    cudaGetSymbolAddress((void**)&k,  g_k);
    cudaGetSymbolAddress((void**)&v,  g_v);
    cudaGetSymbolAddress((void**)&ao, g_ao);

    // opt-in large dynamic smem for the GEMM (done every call; cheap, capturable)
    cudaFuncSetAttribute(tf32_gemm_bias,
                         cudaFuncAttributeMaxDynamicSharedMemorySize, GEMM_SMEM_BYTES);

    // Q projection (tf32 mma, double-buffered)
    tf32_gemm_bias<<<dim3(D_MODEL / GBN, NTOK / GBM), 256, GEMM_SMEM_BYTES>>>(
        NTOK, D_MODEL, D_MODEL, x, Wq, bq, q);

    // K/V projections fused (fp32)
    kv_proj_kernel<<<dim3(2, NTOK / 64), 128>>>(x, Wk, bk, Wv, bv, k, v);

    // Attention (tf32 mma flash, LDS.64 score path)
    size_t smem = (size_t)(AQ * QP + AK * KP + AK * VP) * 4 + AK * sizeof(float);
    cudaFuncSetAttribute(mqa_attn_tf32,
                         cudaFuncAttributeMaxDynamicSharedMemorySize, (int)smem);
    mqa_attn_tf32<<<dim3(SEQ / AQ, N_HEADS, BATCH), 256, smem>>>(q, k, v, mask, ao);

    // Output projection (tf32 mma)
    tf32_gemm_bias<<<dim3(D_MODEL / GBN, NTOK / GBM), 256, GEMM_SMEM_BYTES>>>(
        NTOK, D_MODEL, D_MODEL, ao, Wo, bo, out);
}

// round 6
// speedup vs baseline: 1.2632x; 1.2632x over previous
#include <cuda_runtime.h>
#include <cstdint>
#include <math.h>

#define D_MODEL  2048
#define N_HEADS  16
#define HEAD_DIM 128
#define BATCH    2
#define SEQ      2048
#define NTOK     (BATCH * SEQ)

__device__ float    g_q  [NTOK * D_MODEL];
__device__ float    g_k  [NTOK * HEAD_DIM];
__device__ float    g_v  [NTOK * HEAD_DIM];
__device__ float    g_ao [NTOK * D_MODEL];
__device__ uint32_t g_wqt[D_MODEL * D_MODEL];   // Wq^T, tf32 bits, [N][K]
__device__ uint32_t g_wot[D_MODEL * D_MODEL];   // Wo^T, tf32 bits, [N][K]

// ---------------------------------------------------------------------------
// Helpers
// ---------------------------------------------------------------------------
__device__ __forceinline__ uint32_t f2tf32(float x) {
    uint32_t r;
    asm("cvt.rna.tf32.f32 %0, %1;" : "=r"(r) : "f"(x));
    return r;
}

__device__ __forceinline__ void mma_tf32(float* d,
    uint32_t a0, uint32_t a1, uint32_t a2, uint32_t a3,
    uint32_t b0, uint32_t b1)
{
    asm volatile(
        "mma.sync.aligned.m16n8k8.row.col.f32.tf32.tf32.f32 "
        "{%0,%1,%2,%3},{%4,%5,%6,%7},{%8,%9},{%0,%1,%2,%3};"
        : "+f"(d[0]), "+f"(d[1]), "+f"(d[2]), "+f"(d[3])
        : "r"(a0), "r"(a1), "r"(a2), "r"(a3), "r"(b0), "r"(b1));
}

__device__ __forceinline__ void ldsm_x4(uint32_t& r0, uint32_t& r1,
                                        uint32_t& r2, uint32_t& r3,
                                        uint32_t addr)
{
    asm volatile("ldmatrix.sync.aligned.m8n8.x4.shared.b16 {%0,%1,%2,%3}, [%4];"
                 : "=r"(r0), "=r"(r1), "=r"(r2), "=r"(r3) : "r"(addr));
}

// ---------------------------------------------------------------------------
// Transpose + tf32-convert: dst[N][K] = tf32(src[K][N]).  32x32 tiles.
// ---------------------------------------------------------------------------
__global__ __launch_bounds__(256) void transpose_tf32(
    const float* __restrict__ src, uint32_t* __restrict__ dst)
{
    __shared__ uint32_t tile[32][33];
    int x = blockIdx.x * 32 + threadIdx.x;   // n in src
    int y = blockIdx.y * 32 + threadIdx.y;   // k in src
#pragma unroll
    for (int j = 0; j < 32; j += 8)
        tile[threadIdx.y + j][threadIdx.x] =
            f2tf32(src[(size_t)(y + j) * D_MODEL + x]);
    __syncthreads();
    x = blockIdx.y * 32 + threadIdx.x;       // k in dst
    y = blockIdx.x * 32 + threadIdx.y;       // n in dst
#pragma unroll
    for (int j = 0; j < 32; j += 8)
        dst[(size_t)(y + j) * D_MODEL + x] = tile[threadIdx.x][threadIdx.y + j];
}

// ---------------------------------------------------------------------------
// TF32 GEMM (ldmatrix): C(MxN) = A(MxK) @ Bt^T + bias, Bt = [N][K] tf32 bits.
// 128x128x32 tile, 8 warps @64x32. As[m][k] pad36, Bs[n][k] pad36. Static smem.
// ---------------------------------------------------------------------------
#define GBM 128
#define GBN 128
#define GBK 32
#define ASTR 36
#define BSTR2 36

__global__ __launch_bounds__(256, 2) void tf32_gemm_bias(
    int M, int N, int K,
    const float* __restrict__ A,
    const uint32_t* __restrict__ Bt,
    const float* __restrict__ bias,
    float* __restrict__ C)
{
    __shared__ uint32_t As[GBM * ASTR];
    __shared__ uint32_t Bs[GBN * BSTR2];

    const int tid  = threadIdx.x;
    const int wid  = tid >> 5;
    const int lane = tid & 31;
    const int g    = lane >> 2;
    const int t4   = lane & 3;
    const int wm   = (wid >> 2) * 64;
    const int wn   = (wid & 3) * 32;

    const float*    Ab = A  + (size_t)blockIdx.y * GBM * K;
    const uint32_t* Bb = Bt + (size_t)blockIdx.x * GBN * K;

    // tile loaders: row = tid>>3 (+32i), wordcol = (tid&7)*4
    const int lrow = tid >> 3;
    const int lcol = (tid & 7) * 4;

    // ldmatrix lane->address decomposition
    const int a_row = (lane & 7) + ((lane >> 3) & 1) * 8;   // row within 16
    const int a_kh  = ((lane >> 4) & 1) * 4;                // k half (words)
    const int b_row = (lane & 7) + ((lane >> 4) & 1) * 8;   // n within 16
    const int b_kh  = ((lane >> 3) & 1) * 4;

    const uint32_t As_b = (uint32_t)__cvta_generic_to_shared(As);
    const uint32_t Bs_b = (uint32_t)__cvta_generic_to_shared(Bs);

    float acc[4][4][4];
#pragma unroll
    for (int mi = 0; mi < 4; mi++)
#pragma unroll
        for (int ni = 0; ni < 4; ni++)
#pragma unroll
            for (int r = 0; r < 4; r++) acc[mi][ni][r] = 0.0f;

    for (int k0 = 0; k0 < K; k0 += GBK) {
        // A tile: LDG.128 -> cvt -> STS.128 (plain [m][k])
#pragma unroll
        for (int i = 0; i < 4; i++) {
            int row = lrow + 32 * i;
            float4 a = *(const float4*)&Ab[(size_t)row * K + k0 + lcol];
            uint4 u = make_uint4(f2tf32(a.x), f2tf32(a.y), f2tf32(a.z), f2tf32(a.w));
            *(uint4*)&As[row * ASTR + lcol] = u;
        }
        // B tile: pre-converted tf32, straight copy [n][k]
#pragma unroll
        for (int i = 0; i < 4; i++) {
            int row = lrow + 32 * i;
            uint4 u = *(const uint4*)&Bb[(size_t)row * K + k0 + lcol];
            *(uint4*)&Bs[row * BSTR2 + lcol] = u;
        }
        __syncthreads();

#pragma unroll
        for (int ks = 0; ks < 4; ks++) {
            uint32_t a[4][4];
#pragma unroll
            for (int mi = 0; mi < 4; mi++) {
                uint32_t addr = As_b +
                    ((wm + mi * 16 + a_row) * ASTR + ks * 8 + a_kh) * 4;
                ldsm_x4(a[mi][0], a[mi][1], a[mi][2], a[mi][3], addr);
            }
            uint32_t bf[2][4];
#pragma unroll
            for (int p = 0; p < 2; p++) {
                uint32_t addr = Bs_b +
                    ((wn + p * 16 + b_row) * BSTR2 + ks * 8 + b_kh) * 4;
                ldsm_x4(bf[p][0], bf[p][1], bf[p][2], bf[p][3], addr);
            }
#pragma unroll
            for (int p = 0; p < 2; p++)
#pragma unroll
                for (int hh = 0; hh < 2; hh++) {
                    const int ni = p * 2 + hh;
#pragma unroll
                    for (int mi = 0; mi < 4; mi++)
                        mma_tf32(acc[mi][ni],
                                 a[mi][0], a[mi][1], a[mi][2], a[mi][3],
                                 bf[p][hh * 2], bf[p][hh * 2 + 1]);
                }
        }
        __syncthreads();
    }

    const int rowBase = blockIdx.y * GBM + wm;
    const int colBase = blockIdx.x * GBN + wn;
#pragma unroll
    for (int mi = 0; mi < 4; mi++) {
#pragma unroll
        for (int ni = 0; ni < 4; ni++) {
            const int col = colBase + ni * 8 + 2 * t4;
            const int r0  = rowBase + mi * 16 + g;
            float2 v0, v1;
            v0.x = acc[mi][ni][0] + bias[col];
            v0.y = acc[mi][ni][1] + bias[col + 1];
            v1.x = acc[mi][ni][2] + bias[col];
            v1.y = acc[mi][ni][3] + bias[col + 1];
            *(float2*)&C[(size_t)r0 * N + col]       = v0;
            *(float2*)&C[(size_t)(r0 + 8) * N + col] = v1;
        }
    }
}

// ---------------------------------------------------------------------------
// Fused K/V projection (fp32), unchanged from R3.
// ---------------------------------------------------------------------------
__global__ __launch_bounds__(128) void kv_proj_kernel(
    const float* __restrict__ x,
    const float* __restrict__ Wk, const float* __restrict__ bk,
    const float* __restrict__ Wv, const float* __restrict__ bv,
    float* __restrict__ Kout, float* __restrict__ Vout)
{
    const float* W    = blockIdx.x ? Wv : Wk;
    const float* bias = blockIdx.x ? bv : bk;
    float*       out  = blockIdx.x ? Vout : Kout;

    __shared__ float As_[16][68];
    __shared__ float Bs_[16][128];

    const int tid = threadIdx.x;
    const int tr  = tid / 16;
    const int tc  = tid % 16;

    float acc[8][8];
#pragma unroll
    for (int i = 0; i < 8; i++)
#pragma unroll
        for (int j = 0; j < 8; j++) acc[i][j] = 0.0f;

    const float* Ab = x + (size_t)blockIdx.y * 64 * D_MODEL;
    const int ar = tid >> 2;
    const int ac = (tid & 3) * 4;
    const int br = tid >> 5;
    const int bc = (tid & 31) * 4;

    for (int k0 = 0; k0 < D_MODEL; k0 += 16) {
#pragma unroll
        for (int rr = 0; rr < 2; rr++) {
            int row = ar + rr * 32;
            float4 a = *(const float4*)&Ab[(size_t)row * D_MODEL + k0 + ac];
            As_[ac + 0][row] = a.x;
            As_[ac + 1][row] = a.y;
            As_[ac + 2][row] = a.z;
            As_[ac + 3][row] = a.w;
        }
#pragma unroll
        for (int rr = 0; rr < 4; rr++) {
            int row = br + rr * 4;
            *(float4*)&Bs_[row][bc] =
                *(const float4*)&W[(size_t)(k0 + row) * HEAD_DIM + bc];
        }
        __syncthreads();

#pragma unroll
        for (int kk = 0; kk < 16; kk++) {
            float regM[8], regN[8];
#pragma unroll
            for (int i = 0; i < 8; i++) regM[i] = As_[kk][tr * 8 + i];
#pragma unroll
            for (int j = 0; j < 8; j++) regN[j] = Bs_[kk][tc * 8 + j];
#pragma unroll
            for (int i = 0; i < 8; i++)
#pragma unroll
                for (int j = 0; j < 8; j++)
                    acc[i][j] += regM[i] * regN[j];
        }
        __syncthreads();
    }

    const int rowBase = blockIdx.y * 64 + tr * 8;
    const int colBase = tc * 8;
#pragma unroll
    for (int i = 0; i < 8; i++) {
#pragma unroll
        for (int j = 0; j < 8; j += 4) {
            float4 t;
            t.x = acc[i][j + 0] + bias[colBase + j + 0];
            t.y = acc[i][j + 1] + bias[colBase + j + 1];
            t.z = acc[i][j + 2] + bias[colBase + j + 2];
            t.w = acc[i][j + 3] + bias[colBase + j + 3];
            *(float4*)&out[(size_t)(rowBase + i) * HEAD_DIM + colBase + j] = t;
        }
    }
}

// ---------------------------------------------------------------------------
// TF32 MMA flash attention (R3 base + ldmatrix score path).
// BQ=128, BKT=64, 8 warps. Layouts identical to R3 (plain, k-contiguous).
// ---------------------------------------------------------------------------
#define AQ 128
#define AK 64
#define QP 132
#define KP 132
#define VP 136

__global__ __launch_bounds__(256) void mqa_attn_tf32(
    const float* __restrict__ Q,
    const float* __restrict__ Kg,
    const float* __restrict__ Vg,
    const int* __restrict__ mask,
    float* __restrict__ Og)
{
    extern __shared__ uint32_t sm_u[];
    uint32_t* Qs   = sm_u;                 // AQ x QP
    uint32_t* Ks   = Qs + AQ * QP;         // AK x KP
    uint32_t* Vs   = Ks + AK * KP;         // AK x VP
    float*   sbias = (float*)(Vs + AK * VP);  // AK

    const int tid  = threadIdx.x;
    const int wid  = tid >> 5;
    const int lane = tid & 31;
    const int g    = lane >> 2;
    const int t4   = lane & 3;
    const int b  = blockIdx.z, h = blockIdx.y;
    const int q0 = blockIdx.x * AQ;
    const int wrow = wid * 16;

    // ldmatrix lane decomposition (same mapping as GEMM)
    const int a_row = (lane & 7) + ((lane >> 3) & 1) * 8;
    const int a_kh  = ((lane >> 4) & 1) * 4;
    const int b_row = (lane & 7) + ((lane >> 4) & 1) * 8;
    const int b_kh  = ((lane >> 3) & 1) * 4;
    const uint32_t Qs_b = (uint32_t)__cvta_generic_to_shared(Qs);
    const uint32_t Ks_b = (uint32_t)__cvta_generic_to_shared(Ks);

    // Load Q tile (plain tf32)
    const float* Qp = Q + ((size_t)(b * SEQ + q0)) * D_MODEL + h * HEAD_DIM;
    for (int i = tid; i < AQ * HEAD_DIM / 4; i += 256) {
        int r = i >> 5, c = (i & 31) << 2;
        float4 qv = *(const float4*)&Qp[(size_t)r * D_MODEL + c];
        uint4 u = make_uint4(f2tf32(qv.x), f2tf32(qv.y), f2tf32(qv.z), f2tf32(qv.w));
        *(uint4*)&Qs[r * QP + c] = u;
    }

    float m0 = -1e30f, m1 = -1e30f, l0 = 0.0f, l1 = 0.0f;
    float o[16][4];
#pragma unroll
    for (int n = 0; n < 16; n++)
#pragma unroll
        for (int r = 0; r < 4; r++) o[n][r] = 0.0f;

    const float scale = 0.08838834764831845f;

    for (int k0 = 0; k0 < SEQ; k0 += AK) {
        __syncthreads();
        const float* Kp = Kg + ((size_t)(b * SEQ + k0)) * HEAD_DIM;
        const float* Vp = Vg + ((size_t)(b * SEQ + k0)) * HEAD_DIM;
        for (int i = tid; i < AK * HEAD_DIM / 4; i += 256) {
            int r = i >> 5, c = (i & 31) << 2;
            float4 kv = *(const float4*)&Kp[(size_t)r * HEAD_DIM + c];
            uint4 ku = make_uint4(f2tf32(kv.x), f2tf32(kv.y), f2tf32(kv.z), f2tf32(kv.w));
            *(uint4*)&Ks[r * KP + c] = ku;
            float4 vv = *(const float4*)&Vp[(size_t)r * HEAD_DIM + c];
            uint4 vu = make_uint4(f2tf32(vv.x), f2tf32(vv.y), f2tf32(vv.z), f2tf32(vv.w));
            *(uint4*)&Vs[r * VP + c] = vu;
        }
        if (tid < AK)
            sbias[tid] = mask[(size_t)b * SEQ + k0 + tid] ? 0.0f : -1e9f;
        __syncthreads();

        // ---- Scores: S = Q @ K^T via ldmatrix ----
        float s[8][4];
#pragma unroll
        for (int j = 0; j < 8; j++)
#pragma unroll
            for (int r = 0; r < 4; r++) s[j][r] = 0.0f;

#pragma unroll
        for (int ks = 0; ks < 16; ks++) {
            uint32_t aq[4];
            ldsm_x4(aq[0], aq[1], aq[2], aq[3],
                    Qs_b + ((wrow + a_row) * QP + ks * 8 + a_kh) * 4);
#pragma unroll
            for (int p = 0; p < 4; p++) {
                uint32_t bf[4];
                ldsm_x4(bf[0], bf[1], bf[2], bf[3],
                        Ks_b + ((p * 16 + b_row) * KP + ks * 8 + b_kh) * 4);
                mma_tf32(s[2 * p],     aq[0], aq[1], aq[2], aq[3], bf[0], bf[1]);
                mma_tf32(s[2 * p + 1], aq[0], aq[1], aq[2], aq[3], bf[2], bf[3]);
            }
        }

        // ---- scale + mask, row max ----
        float rmax0 = -1e30f, rmax1 = -1e30f;
#pragma unroll
        for (int j = 0; j < 8; j++) {
            float2 sb = *(float2*)&sbias[j * 8 + 2 * t4];
            s[j][0] = s[j][0] * scale + sb.x;
            s[j][1] = s[j][1] * scale + sb.y;
            s[j][2] = s[j][2] * scale + sb.x;
            s[j][3] = s[j][3] * scale + sb.y;
            rmax0 = fmaxf(rmax0, fmaxf(s[j][0], s[j][1]));
            rmax1 = fmaxf(rmax1, fmaxf(s[j][2], s[j][3]));
        }
#pragma unroll
        for (int off = 1; off <= 2; off <<= 1) {
            rmax0 = fmaxf(rmax0, __shfl_xor_sync(0xffffffffu, rmax0, off));
            rmax1 = fmaxf(rmax1, __shfl_xor_sync(0xffffffffu, rmax1, off));
        }
        const float mn0 = fmaxf(m0, rmax0);
        const float mn1 = fmaxf(m1, rmax1);
        const float c0 = __expf(m0 - mn0);
        const float c1 = __expf(m1 - mn1);
        m0 = mn0; m1 = mn1;

        float rs0 = 0.0f, rs1 = 0.0f;
        uint32_t pt[8][4];
#pragma unroll
        for (int j = 0; j < 8; j++) {
            float p0 = __expf(s[j][0] - mn0);
            float p1 = __expf(s[j][1] - mn0);
            float p2 = __expf(s[j][2] - mn1);
            float p3 = __expf(s[j][3] - mn1);
            rs0 += p0 + p1;
            rs1 += p2 + p3;
            pt[j][0] = f2tf32(p0);
            pt[j][1] = f2tf32(p1);
            pt[j][2] = f2tf32(p2);
            pt[j][3] = f2tf32(p3);
        }
#pragma unroll
        for (int off = 1; off <= 2; off <<= 1) {
            rs0 += __shfl_xor_sync(0xffffffffu, rs0, off);
            rs1 += __shfl_xor_sync(0xffffffffu, rs1, off);
        }
        l0 = l0 * c0 + rs0;
        l1 = l1 * c1 + rs1;

#pragma unroll
        for (int n = 0; n < 16; n++) {
            o[n][0] *= c0; o[n][1] *= c0;
            o[n][2] *= c1; o[n][3] *= c1;
        }

        // ---- O += P @ V (A-frags from pt via shuffles; V scalar LDS, as R3) ----
        const int src1 = (g << 2) + (t4 >> 1);
        const int src2 = src1 + 2;
        const bool odd = (t4 & 1);
#pragma unroll
        for (int j = 0; j < 8; j++) {
            uint32_t x00 = __shfl_sync(0xffffffffu, pt[j][0], src1);
            uint32_t x01 = __shfl_sync(0xffffffffu, pt[j][1], src1);
            uint32_t x10 = __shfl_sync(0xffffffffu, pt[j][0], src2);
            uint32_t x11 = __shfl_sync(0xffffffffu, pt[j][1], src2);
            uint32_t x20 = __shfl_sync(0xffffffffu, pt[j][2], src1);
            uint32_t x21 = __shfl_sync(0xffffffffu, pt[j][3], src1);
            uint32_t x30 = __shfl_sync(0xffffffffu, pt[j][2], src2);
            uint32_t x31 = __shfl_sync(0xffffffffu, pt[j][3], src2);
            uint32_t a0 = odd ? x01 : x00;
            uint32_t a2 = odd ? x11 : x10;
            uint32_t a1 = odd ? x21 : x20;
            uint32_t a3 = odd ? x31 : x30;
#pragma unroll
            for (int n = 0; n < 16; n++) {
                uint32_t b0 = Vs[(j * 8 + t4    ) * VP + n * 8 + g];
                uint32_t b1 = Vs[(j * 8 + t4 + 4) * VP + n * 8 + g];
                mma_tf32(o[n], a0, a1, a2, a3, b0, b1);
            }
        }
    }

    // ---- Epilogue ----
    const float inv0 = 1.0f / l0;
    const float inv1 = 1.0f / l1;
    float* Op0 = Og + ((size_t)(b * SEQ + q0 + wrow + g    )) * D_MODEL + h * HEAD_DIM;
    float* Op1 = Og + ((size_t)(b * SEQ + q0 + wrow + g + 8)) * D_MODEL + h * HEAD_DIM;
#pragma unroll
    for (int n = 0; n < 16; n++) {
        const int col = n * 8 + 2 * t4;
        float2 v0, v1;
        v0.x = o[n][0] * inv0; v0.y = o[n][1] * inv0;
        v1.x = o[n][2] * inv1; v1.y = o[n][3] * inv1;
        *(float2*)&Op0[col] = v0;
        *(float2*)&Op1[col] = v1;
    }
}

// ---------------------------------------------------------------------------
extern "C" void kernel_launch(void* const* d_in, const int* in_sizes, int n_in,
                              void* d_out, int out_size)
{
    const float* x    = (const float*)d_in[0];
    const int*   mask = (const int*)d_in[1];
    const float* Wq   = (const float*)d_in[2];
    const float* bq   = (const float*)d_in[3];
    const float* Wk   = (const float*)d_in[4];
    const float* bk   = (const float*)d_in[5];
    const float* Wv   = (const float*)d_in[6];
    const float* bv   = (const float*)d_in[7];
    const float* Wo   = (const float*)d_in[8];
    const float* bo   = (const float*)d_in[9];
    float* out = (float*)d_out;

    float *q, *k, *v, *ao;
    uint32_t *wqt, *wot;
    cudaGetSymbolAddress((void**)&q,   g_q);
    cudaGetSymbolAddress((void**)&k,   g_k);
    cudaGetSymbolAddress((void**)&v,   g_v);
    cudaGetSymbolAddress((void**)&ao,  g_ao);
    cudaGetSymbolAddress((void**)&wqt, g_wqt);
    cudaGetSymbolAddress((void**)&wot, g_wot);

    // Pre-transpose + tf32-convert weights (B side of the two big GEMMs)
    transpose_tf32<<<dim3(64, 64), dim3(32, 8)>>>(Wq, wqt);
    transpose_tf32<<<dim3(64, 64), dim3(32, 8)>>>(Wo, wot);

    // Q projection (tf32 mma + ldmatrix)
    tf32_gemm_bias<<<dim3(D_MODEL / GBN, NTOK / GBM), 256>>>(
        NTOK, D_MODEL, D_MODEL, x, wqt, bq, q);

    // K/V projections fused (fp32)
    kv_proj_kernel<<<dim3(2, NTOK / 64), 128>>>(x, Wk, bk, Wv, bv, k, v);

    // Attention (tf32 mma flash + ldmatrix score path)
    size_t smem = (size_t)(AQ * QP + AK * KP + AK * VP) * 4 + AK * sizeof(float);
    cudaFuncSetAttribute(mqa_attn_tf32,
                         cudaFuncAttributeMaxDynamicSharedMemorySize, (int)smem);
    mqa_attn_tf32<<<dim3(SEQ / AQ, N_HEADS, BATCH), 256, smem>>>(q, k, v, mask, ao);

    // Output projection (tf32 mma + ldmatrix)
    tf32_gemm_bias<<<dim3(D_MODEL / GBN, NTOK / GBM), 256>>>(
        NTOK, D_MODEL, D_MODEL, ao, wot, bo, out);
}

// round 7
// speedup vs baseline: 1.3812x; 1.0934x over previous
#include <cuda_runtime.h>
#include <cstdint>
#include <math.h>

#define D_MODEL  2048
#define N_HEADS  16
#define HEAD_DIM 128
#define BATCH    2
#define SEQ      2048
#define NTOK     (BATCH * SEQ)
#define KVSPLIT  4
#define KCHUNK   (D_MODEL / KVSPLIT)   // 512

__device__ float    g_q  [NTOK * D_MODEL];
__device__ float    g_k  [NTOK * HEAD_DIM];
__device__ float    g_v  [NTOK * HEAD_DIM];
__device__ float    g_ao [NTOK * D_MODEL];
__device__ uint32_t g_wqt[D_MODEL * D_MODEL];          // Wq^T tf32 bits [N][K]
__device__ uint32_t g_wot[D_MODEL * D_MODEL];          // Wo^T tf32 bits [N][K]
__device__ float    g_kp [KVSPLIT][NTOK * HEAD_DIM];   // K partials
__device__ float    g_vp [KVSPLIT][NTOK * HEAD_DIM];   // V partials

// ---------------------------------------------------------------------------
// Helpers
// ---------------------------------------------------------------------------
__device__ __forceinline__ uint32_t f2tf32(float x) {
    uint32_t r;
    asm("cvt.rna.tf32.f32 %0, %1;" : "=r"(r) : "f"(x));
    return r;
}

__device__ __forceinline__ void mma_tf32(float* d,
    uint32_t a0, uint32_t a1, uint32_t a2, uint32_t a3,
    uint32_t b0, uint32_t b1)
{
    asm volatile(
        "mma.sync.aligned.m16n8k8.row.col.f32.tf32.tf32.f32 "
        "{%0,%1,%2,%3},{%4,%5,%6,%7},{%8,%9},{%0,%1,%2,%3};"
        : "+f"(d[0]), "+f"(d[1]), "+f"(d[2]), "+f"(d[3])
        : "r"(a0), "r"(a1), "r"(a2), "r"(a3), "r"(b0), "r"(b1));
}

__device__ __forceinline__ void ldsm_x4(uint32_t& r0, uint32_t& r1,
                                        uint32_t& r2, uint32_t& r3,
                                        uint32_t addr)
{
    asm volatile("ldmatrix.sync.aligned.m8n8.x4.shared.b16 {%0,%1,%2,%3}, [%4];"
                 : "=r"(r0), "=r"(r1), "=r"(r2), "=r"(r3) : "r"(addr));
}

// ---------------------------------------------------------------------------
// Transpose + tf32-convert: dst[N][K] = tf32(src[K][N]).  32x32 tiles.
// ---------------------------------------------------------------------------
__global__ __launch_bounds__(256) void transpose_tf32(
    const float* __restrict__ src, uint32_t* __restrict__ dst)
{
    __shared__ uint32_t tile[32][33];
    int x = blockIdx.x * 32 + threadIdx.x;
    int y = blockIdx.y * 32 + threadIdx.y;
#pragma unroll
    for (int j = 0; j < 32; j += 8)
        tile[threadIdx.y + j][threadIdx.x] =
            f2tf32(src[(size_t)(y + j) * D_MODEL + x]);
    __syncthreads();
    x = blockIdx.y * 32 + threadIdx.x;
    y = blockIdx.x * 32 + threadIdx.y;
#pragma unroll
    for (int j = 0; j < 32; j += 8)
        dst[(size_t)(y + j) * D_MODEL + x] = tile[threadIdx.x][threadIdx.y + j];
}

// ---------------------------------------------------------------------------
// TF32 GEMM (ldmatrix), unchanged from R6.
// ---------------------------------------------------------------------------
#define GBM 128
#define GBN 128
#define GBK 32
#define ASTR 36
#define BSTR2 36

__global__ __launch_bounds__(256, 2) void tf32_gemm_bias(
    int M, int N, int K,
    const float* __restrict__ A,
    const uint32_t* __restrict__ Bt,
    const float* __restrict__ bias,
    float* __restrict__ C)
{
    __shared__ uint32_t As[GBM * ASTR];
    __shared__ uint32_t Bs[GBN * BSTR2];

    const int tid  = threadIdx.x;
    const int wid  = tid >> 5;
    const int lane = tid & 31;
    const int g    = lane >> 2;
    const int t4   = lane & 3;
    const int wm   = (wid >> 2) * 64;
    const int wn   = (wid & 3) * 32;

    const float*    Ab = A  + (size_t)blockIdx.y * GBM * K;
    const uint32_t* Bb = Bt + (size_t)blockIdx.x * GBN * K;

    const int lrow = tid >> 3;
    const int lcol = (tid & 7) * 4;

    const int a_row = (lane & 7) + ((lane >> 3) & 1) * 8;
    const int a_kh  = ((lane >> 4) & 1) * 4;
    const int b_row = (lane & 7) + ((lane >> 4) & 1) * 8;
    const int b_kh  = ((lane >> 3) & 1) * 4;

    const uint32_t As_b = (uint32_t)__cvta_generic_to_shared(As);
    const uint32_t Bs_b = (uint32_t)__cvta_generic_to_shared(Bs);

    float acc[4][4][4];
#pragma unroll
    for (int mi = 0; mi < 4; mi++)
#pragma unroll
        for (int ni = 0; ni < 4; ni++)
#pragma unroll
            for (int r = 0; r < 4; r++) acc[mi][ni][r] = 0.0f;

    for (int k0 = 0; k0 < K; k0 += GBK) {
#pragma unroll
        for (int i = 0; i < 4; i++) {
            int row = lrow + 32 * i;
            float4 a = *(const float4*)&Ab[(size_t)row * K + k0 + lcol];
            uint4 u = make_uint4(f2tf32(a.x), f2tf32(a.y), f2tf32(a.z), f2tf32(a.w));
            *(uint4*)&As[row * ASTR + lcol] = u;
        }
#pragma unroll
        for (int i = 0; i < 4; i++) {
            int row = lrow + 32 * i;
            uint4 u = *(const uint4*)&Bb[(size_t)row * K + k0 + lcol];
            *(uint4*)&Bs[row * BSTR2 + lcol] = u;
        }
        __syncthreads();

#pragma unroll
        for (int ks = 0; ks < 4; ks++) {
            uint32_t a[4][4];
#pragma unroll
            for (int mi = 0; mi < 4; mi++) {
                uint32_t addr = As_b +
                    ((wm + mi * 16 + a_row) * ASTR + ks * 8 + a_kh) * 4;
                ldsm_x4(a[mi][0], a[mi][1], a[mi][2], a[mi][3], addr);
            }
            uint32_t bf[2][4];
#pragma unroll
            for (int p = 0; p < 2; p++) {
                uint32_t addr = Bs_b +
                    ((wn + p * 16 + b_row) * BSTR2 + ks * 8 + b_kh) * 4;
                ldsm_x4(bf[p][0], bf[p][1], bf[p][2], bf[p][3], addr);
            }
#pragma unroll
            for (int p = 0; p < 2; p++)
#pragma unroll
                for (int hh = 0; hh < 2; hh++) {
                    const int ni = p * 2 + hh;
#pragma unroll
                    for (int mi = 0; mi < 4; mi++)
                        mma_tf32(acc[mi][ni],
                                 a[mi][0], a[mi][1], a[mi][2], a[mi][3],
                                 bf[p][hh * 2], bf[p][hh * 2 + 1]);
                }
        }
        __syncthreads();
    }

    const int rowBase = blockIdx.y * GBM + wm;
    const int colBase = blockIdx.x * GBN + wn;
#pragma unroll
    for (int mi = 0; mi < 4; mi++) {
#pragma unroll
        for (int ni = 0; ni < 4; ni++) {
            const int col = colBase + ni * 8 + 2 * t4;
            const int r0  = rowBase + mi * 16 + g;
            float2 v0, v1;
            v0.x = acc[mi][ni][0] + bias[col];
            v0.y = acc[mi][ni][1] + bias[col + 1];
            v1.x = acc[mi][ni][2] + bias[col];
            v1.y = acc[mi][ni][3] + bias[col + 1];
            *(float2*)&C[(size_t)r0 * N + col]       = v0;
            *(float2*)&C[(size_t)(r0 + 8) * N + col] = v1;
        }
    }
}

// ---------------------------------------------------------------------------
// K/V projection, split-K x4: partials (no bias) to scratch, fp32.
// grid (2, NTOK/64, KVSPLIT); blockIdx.x: 0->K, 1->V.
// ---------------------------------------------------------------------------
__global__ __launch_bounds__(128) void kv_proj_partial(
    const float* __restrict__ x,
    const float* __restrict__ Wk,
    const float* __restrict__ Wv,
    float* __restrict__ Kpart, float* __restrict__ Vpart)
{
    const float* W   = blockIdx.x ? Wv : Wk;
    float*       out = (blockIdx.x ? Vpart : Kpart)
                     + (size_t)blockIdx.z * NTOK * HEAD_DIM;

    __shared__ float As_[16][68];
    __shared__ float Bs_[16][128];

    const int tid = threadIdx.x;
    const int tr  = tid / 16;
    const int tc  = tid % 16;

    float acc[8][8];
#pragma unroll
    for (int i = 0; i < 8; i++)
#pragma unroll
        for (int j = 0; j < 8; j++) acc[i][j] = 0.0f;

    const float* Ab = x + (size_t)blockIdx.y * 64 * D_MODEL;
    const int ar = tid >> 2;
    const int ac = (tid & 3) * 4;
    const int br = tid >> 5;
    const int bc = (tid & 31) * 4;

    const int kbeg = blockIdx.z * KCHUNK;
    const int kend = kbeg + KCHUNK;

    for (int k0 = kbeg; k0 < kend; k0 += 16) {
#pragma unroll
        for (int rr = 0; rr < 2; rr++) {
            int row = ar + rr * 32;
            float4 a = *(const float4*)&Ab[(size_t)row * D_MODEL + k0 + ac];
            As_[ac + 0][row] = a.x;
            As_[ac + 1][row] = a.y;
            As_[ac + 2][row] = a.z;
            As_[ac + 3][row] = a.w;
        }
#pragma unroll
        for (int rr = 0; rr < 4; rr++) {
            int row = br + rr * 4;
            *(float4*)&Bs_[row][bc] =
                *(const float4*)&W[(size_t)(k0 + row) * HEAD_DIM + bc];
        }
        __syncthreads();

#pragma unroll
        for (int kk = 0; kk < 16; kk++) {
            float regM[8], regN[8];
#pragma unroll
            for (int i = 0; i < 8; i++) regM[i] = As_[kk][tr * 8 + i];
#pragma unroll
            for (int j = 0; j < 8; j++) regN[j] = Bs_[kk][tc * 8 + j];
#pragma unroll
            for (int i = 0; i < 8; i++)
#pragma unroll
                for (int j = 0; j < 8; j++)
                    acc[i][j] += regM[i] * regN[j];
        }
        __syncthreads();
    }

    const int rowBase = blockIdx.y * 64 + tr * 8;
    const int colBase = tc * 8;
#pragma unroll
    for (int i = 0; i < 8; i++)
#pragma unroll
        for (int j = 0; j < 8; j += 4)
            *(float4*)&out[(size_t)(rowBase + i) * HEAD_DIM + colBase + j] =
                make_float4(acc[i][j], acc[i][j + 1], acc[i][j + 2], acc[i][j + 3]);
}

// Deterministic fixed-order reduce + bias. 1 float4 per thread per array.
__global__ __launch_bounds__(256) void kv_reduce(
    const float* __restrict__ Kpart, const float* __restrict__ Vpart,
    const float* __restrict__ bk,    const float* __restrict__ bv,
    float* __restrict__ Kout,        float* __restrict__ Vout)
{
    const int i = blockIdx.x * 256 + threadIdx.x;        // float4 index
    const int e = i * 4;
    const float4 bkv = *(const float4*)&bk[e & (HEAD_DIM - 1)];
    const float4 bvv = *(const float4*)&bv[e & (HEAD_DIM - 1)];
    float4 ks = make_float4(bkv.x, bkv.y, bkv.z, bkv.w);
    float4 vs = make_float4(bvv.x, bvv.y, bvv.z, bvv.w);
#pragma unroll
    for (int p = 0; p < KVSPLIT; p++) {
        float4 kp = *(const float4*)&Kpart[(size_t)p * NTOK * HEAD_DIM + e];
        ks.x += kp.x; ks.y += kp.y; ks.z += kp.z; ks.w += kp.w;
        float4 vp = *(const float4*)&Vpart[(size_t)p * NTOK * HEAD_DIM + e];
        vs.x += vp.x; vs.y += vp.y; vs.z += vp.z; vs.w += vp.w;
    }
    *(float4*)&Kout[e] = ks;
    *(float4*)&Vout[e] = vs;
}

// ---------------------------------------------------------------------------
// TF32 MMA flash attention: R6 + register prefetch of next K/V tiles.
// ---------------------------------------------------------------------------
#define AQ 128
#define AK 64
#define QP 132
#define KP 132
#define VP 136

__global__ __launch_bounds__(256) void mqa_attn_tf32(
    const float* __restrict__ Q,
    const float* __restrict__ Kg,
    const float* __restrict__ Vg,
    const int* __restrict__ mask,
    float* __restrict__ Og)
{
    extern __shared__ uint32_t sm_u[];
    uint32_t* Qs   = sm_u;
    uint32_t* Ks   = Qs + AQ * QP;
    uint32_t* Vs   = Ks + AK * KP;
    float*   sbias = (float*)(Vs + AK * VP);

    const int tid  = threadIdx.x;
    const int wid  = tid >> 5;
    const int lane = tid & 31;
    const int g    = lane >> 2;
    const int t4   = lane & 3;
    const int b  = blockIdx.z, h = blockIdx.y;
    const int q0 = blockIdx.x * AQ;
    const int wrow = wid * 16;

    const int a_row = (lane & 7) + ((lane >> 3) & 1) * 8;
    const int a_kh  = ((lane >> 4) & 1) * 4;
    const int b_row = (lane & 7) + ((lane >> 4) & 1) * 8;
    const int b_kh  = ((lane >> 3) & 1) * 4;
    const uint32_t Qs_b = (uint32_t)__cvta_generic_to_shared(Qs);
    const uint32_t Ks_b = (uint32_t)__cvta_generic_to_shared(Ks);

    // per-thread K/V staging coordinates (8 float4 each covering 64x128)
    const int pr0 = tid >> 5;            // row base (+8u)
    const int pc  = (tid & 31) << 2;     // col

    // Load Q tile (plain tf32)
    const float* Qp = Q + ((size_t)(b * SEQ + q0)) * D_MODEL + h * HEAD_DIM;
    for (int i = tid; i < AQ * HEAD_DIM / 4; i += 256) {
        int r = i >> 5, c = (i & 31) << 2;
        float4 qv = *(const float4*)&Qp[(size_t)r * D_MODEL + c];
        uint4 u = make_uint4(f2tf32(qv.x), f2tf32(qv.y), f2tf32(qv.z), f2tf32(qv.w));
        *(uint4*)&Qs[r * QP + c] = u;
    }

    // Prefetch tile 0 into registers
    float4 kreg[8], vreg[8];
    {
        const float* Kp = Kg + ((size_t)(b * SEQ)) * HEAD_DIM;
        const float* Vp = Vg + ((size_t)(b * SEQ)) * HEAD_DIM;
#pragma unroll
        for (int u = 0; u < 8; u++) {
            const size_t off = (size_t)(pr0 + 8 * u) * HEAD_DIM + pc;
            kreg[u] = *(const float4*)&Kp[off];
            vreg[u] = *(const float4*)&Vp[off];
        }
    }

    float m0 = -1e30f, m1 = -1e30f, l0 = 0.0f, l1 = 0.0f;
    float o[16][4];
#pragma unroll
    for (int n = 0; n < 16; n++)
#pragma unroll
        for (int r = 0; r < 4; r++) o[n][r] = 0.0f;

    const float scale = 0.08838834764831845f;

    for (int k0 = 0; k0 < SEQ; k0 += AK) {
        __syncthreads();
        // Store staged tile to smem (cvt on store)
#pragma unroll
        for (int u = 0; u < 8; u++) {
            const int r = pr0 + 8 * u;
            uint4 ku = make_uint4(f2tf32(kreg[u].x), f2tf32(kreg[u].y),
                                  f2tf32(kreg[u].z), f2tf32(kreg[u].w));
            *(uint4*)&Ks[r * KP + pc] = ku;
            uint4 vu = make_uint4(f2tf32(vreg[u].x), f2tf32(vreg[u].y),
                                  f2tf32(vreg[u].z), f2tf32(vreg[u].w));
            *(uint4*)&Vs[r * VP + pc] = vu;
        }
        if (tid < AK)
            sbias[tid] = mask[(size_t)b * SEQ + k0 + tid] ? 0.0f : -1e9f;
        __syncthreads();

        // Prefetch next tile (latency hidden under compute below)
        if (k0 + AK < SEQ) {
            const float* Kp = Kg + ((size_t)(b * SEQ + k0 + AK)) * HEAD_DIM;
            const float* Vp = Vg + ((size_t)(b * SEQ + k0 + AK)) * HEAD_DIM;
#pragma unroll
            for (int u = 0; u < 8; u++) {
                const size_t off = (size_t)(pr0 + 8 * u) * HEAD_DIM + pc;
                kreg[u] = *(const float4*)&Kp[off];
                vreg[u] = *(const float4*)&Vp[off];
            }
        }

        // ---- Scores: S = Q @ K^T via ldmatrix ----
        float s[8][4];
#pragma unroll
        for (int j = 0; j < 8; j++)
#pragma unroll
            for (int r = 0; r < 4; r++) s[j][r] = 0.0f;

#pragma unroll
        for (int ks = 0; ks < 16; ks++) {
            uint32_t aq[4];
            ldsm_x4(aq[0], aq[1], aq[2], aq[3],
                    Qs_b + ((wrow + a_row) * QP + ks * 8 + a_kh) * 4);
#pragma unroll
            for (int p = 0; p < 4; p++) {
                uint32_t bf[4];
                ldsm_x4(bf[0], bf[1], bf[2], bf[3],
                        Ks_b + ((p * 16 + b_row) * KP + ks * 8 + b_kh) * 4);
                mma_tf32(s[2 * p],     aq[0], aq[1], aq[2], aq[3], bf[0], bf[1]);
                mma_tf32(s[2 * p + 1], aq[0], aq[1], aq[2], aq[3], bf[2], bf[3]);
            }
        }

        // ---- scale + mask, row max ----
        float rmax0 = -1e30f, rmax1 = -1e30f;
#pragma unroll
        for (int j = 0; j < 8; j++) {
            float2 sb = *(float2*)&sbias[j * 8 + 2 * t4];
            s[j][0] = s[j][0] * scale + sb.x;
            s[j][1] = s[j][1] * scale + sb.y;
            s[j][2] = s[j][2] * scale + sb.x;
            s[j][3] = s[j][3] * scale + sb.y;
            rmax0 = fmaxf(rmax0, fmaxf(s[j][0], s[j][1]));
            rmax1 = fmaxf(rmax1, fmaxf(s[j][2], s[j][3]));
        }
#pragma unroll
        for (int off = 1; off <= 2; off <<= 1) {
            rmax0 = fmaxf(rmax0, __shfl_xor_sync(0xffffffffu, rmax0, off));
            rmax1 = fmaxf(rmax1, __shfl_xor_sync(0xffffffffu, rmax1, off));
        }
        const float mn0 = fmaxf(m0, rmax0);
        const float mn1 = fmaxf(m1, rmax1);
        const float c0 = __expf(m0 - mn0);
        const float c1 = __expf(m1 - mn1);
        m0 = mn0; m1 = mn1;

        float rs0 = 0.0f, rs1 = 0.0f;
        uint32_t pt[8][4];
#pragma unroll
        for (int j = 0; j < 8; j++) {
            float p0 = __expf(s[j][0] - mn0);
            float p1 = __expf(s[j][1] - mn0);
            float p2 = __expf(s[j][2] - mn1);
            float p3 = __expf(s[j][3] - mn1);
            rs0 += p0 + p1;
            rs1 += p2 + p3;
            pt[j][0] = f2tf32(p0);
            pt[j][1] = f2tf32(p1);
            pt[j][2] = f2tf32(p2);
            pt[j][3] = f2tf32(p3);
        }
#pragma unroll
        for (int off = 1; off <= 2; off <<= 1) {
            rs0 += __shfl_xor_sync(0xffffffffu, rs0, off);
            rs1 += __shfl_xor_sync(0xffffffffu, rs1, off);
        }
        l0 = l0 * c0 + rs0;
        l1 = l1 * c1 + rs1;

#pragma unroll
        for (int n = 0; n < 16; n++) {
            o[n][0] *= c0; o[n][1] *= c0;
            o[n][2] *= c1; o[n][3] *= c1;
        }

        // ---- O += P @ V ----
        const int src1 = (g << 2) + (t4 >> 1);
        const int src2 = src1 + 2;
        const bool odd = (t4 & 1);
#pragma unroll
        for (int j = 0; j < 8; j++) {
            uint32_t x00 = __shfl_sync(0xffffffffu, pt[j][0], src1);
            uint32_t x01 = __shfl_sync(0xffffffffu, pt[j][1], src1);
            uint32_t x10 = __shfl_sync(0xffffffffu, pt[j][0], src2);
            uint32_t x11 = __shfl_sync(0xffffffffu, pt[j][1], src2);
            uint32_t x20 = __shfl_sync(0xffffffffu, pt[j][2], src1);
            uint32_t x21 = __shfl_sync(0xffffffffu, pt[j][3], src1);
            uint32_t x30 = __shfl_sync(0xffffffffu, pt[j][2], src2);
            uint32_t x31 = __shfl_sync(0xffffffffu, pt[j][3], src2);
            uint32_t a0 = odd ? x01 : x00;
            uint32_t a2 = odd ? x11 : x10;
            uint32_t a1 = odd ? x21 : x20;
            uint32_t a3 = odd ? x31 : x30;
#pragma unroll
            for (int n = 0; n < 16; n++) {
                uint32_t b0 = Vs[(j * 8 + t4    ) * VP + n * 8 + g];
                uint32_t b1 = Vs[(j * 8 + t4 + 4) * VP + n * 8 + g];
                mma_tf32(o[n], a0, a1, a2, a3, b0, b1);
            }
        }
    }

    // ---- Epilogue ----
    const float inv0 = 1.0f / l0;
    const float inv1 = 1.0f / l1;
    float* Op0 = Og + ((size_t)(b * SEQ + q0 + wrow + g    )) * D_MODEL + h * HEAD_DIM;
    float* Op1 = Og + ((size_t)(b * SEQ + q0 + wrow + g + 8)) * D_MODEL + h * HEAD_DIM;
#pragma unroll
    for (int n = 0; n < 16; n++) {
        const int col = n * 8 + 2 * t4;
        float2 v0, v1;
        v0.x = o[n][0] * inv0; v0.y = o[n][1] * inv0;
        v1.x = o[n][2] * inv1; v1.y = o[n][3] * inv1;
        *(float2*)&Op0[col] = v0;
        *(float2*)&Op1[col] = v1;
    }
}

// ---------------------------------------------------------------------------
extern "C" void kernel_launch(void* const* d_in, const int* in_sizes, int n_in,
                              void* d_out, int out_size)
{
    const float* x    = (const float*)d_in[0];
    const int*   mask = (const int*)d_in[1];
    const float* Wq   = (const float*)d_in[2];
    const float* bq   = (const float*)d_in[3];
    const float* Wk   = (const float*)d_in[4];
    const float* bk   = (const float*)d_in[5];
    const float* Wv   = (const float*)d_in[6];
    const float* bv   = (const float*)d_in[7];
    const float* Wo   = (const float*)d_in[8];
    const float* bo   = (const float*)d_in[9];
    float* out = (float*)d_out;

    float *q, *k, *v, *ao, *kp, *vp;
    uint32_t *wqt, *wot;
    cudaGetSymbolAddress((void**)&q,   g_q);
    cudaGetSymbolAddress((void**)&k,   g_k);
    cudaGetSymbolAddress((void**)&v,   g_v);
    cudaGetSymbolAddress((void**)&ao,  g_ao);
    cudaGetSymbolAddress((void**)&kp,  g_kp);
    cudaGetSymbolAddress((void**)&vp,  g_vp);
    cudaGetSymbolAddress((void**)&wqt, g_wqt);
    cudaGetSymbolAddress((void**)&wot, g_wot);

    // Weight transposes (B side of the two big GEMMs)
    transpose_tf32<<<dim3(64, 64), dim3(32, 8)>>>(Wq, wqt);
    transpose_tf32<<<dim3(64, 64), dim3(32, 8)>>>(Wo, wot);

    // Q projection
    tf32_gemm_bias<<<dim3(D_MODEL / GBN, NTOK / GBM), 256>>>(
        NTOK, D_MODEL, D_MODEL, x, wqt, bq, q);

    // K/V projections: split-K partials + deterministic reduce
    kv_proj_partial<<<dim3(2, NTOK / 64, KVSPLIT), 128>>>(x, Wk, Wv, kp, vp);
    kv_reduce<<<NTOK * HEAD_DIM / 4 / 256, 256>>>(kp, vp, bk, bv, k, v);

    // Attention
    size_t smem = (size_t)(AQ * QP + AK * KP + AK * VP) * 4 + AK * sizeof(float);
    cudaFuncSetAttribute(mqa_attn_tf32,
                         cudaFuncAttributeMaxDynamicSharedMemorySize, (int)smem);
    mqa_attn_tf32<<<dim3(SEQ / AQ, N_HEADS, BATCH), 256, smem>>>(q, k, v, mask, ao);

    // Output projection
    tf32_gemm_bias<<<dim3(D_MODEL / GBN, NTOK / GBM), 256>>>(
        NTOK, D_MODEL, D_MODEL, ao, wot, bo, out);
}

// round 8
// speedup vs baseline: 1.5350x; 1.1114x over previous
#include <cuda_runtime.h>
#include <cstdint>
#include <math.h>

#define D_MODEL  2048
#define N_HEADS  16
#define HEAD_DIM 128
#define BATCH    2
#define SEQ      2048
#define NTOK     (BATCH * SEQ)
#define KVSPLIT  4
#define KCHUNK   (D_MODEL / KVSPLIT)   // 512
#define KVN      256                   // combined K|V output width

__device__ float    g_q   [NTOK * D_MODEL];
__device__ float    g_k   [NTOK * HEAD_DIM];
__device__ uint32_t g_vt  [HEAD_DIM * NTOK];          // V^T, tf32 bits [d][token]
__device__ float    g_ao  [NTOK * D_MODEL];
__device__ uint32_t g_wqt [D_MODEL * D_MODEL];        // Wq^T tf32 [N][K]
__device__ uint32_t g_wot [D_MODEL * D_MODEL];        // Wo^T tf32 [N][K]
__device__ uint32_t g_wkvt[KVN * D_MODEL];            // (Wk|Wv)^T tf32 [256][2048]
__device__ float    g_kvp [KVSPLIT][NTOK * KVN];      // split-K partials

// ---------------------------------------------------------------------------
// Helpers
// ---------------------------------------------------------------------------
__device__ __forceinline__ uint32_t f2tf32(float x) {
    uint32_t r;
    asm("cvt.rna.tf32.f32 %0, %1;" : "=r"(r) : "f"(x));
    return r;
}

__device__ __forceinline__ void mma_tf32(float* d,
    uint32_t a0, uint32_t a1, uint32_t a2, uint32_t a3,
    uint32_t b0, uint32_t b1)
{
    asm volatile(
        "mma.sync.aligned.m16n8k8.row.col.f32.tf32.tf32.f32 "
        "{%0,%1,%2,%3},{%4,%5,%6,%7},{%8,%9},{%0,%1,%2,%3};"
        : "+f"(d[0]), "+f"(d[1]), "+f"(d[2]), "+f"(d[3])
        : "r"(a0), "r"(a1), "r"(a2), "r"(a3), "r"(b0), "r"(b1));
}

__device__ __forceinline__ void ldsm_x4(uint32_t& r0, uint32_t& r1,
                                        uint32_t& r2, uint32_t& r3,
                                        uint32_t addr)
{
    asm volatile("ldmatrix.sync.aligned.m8n8.x4.shared.b16 {%0,%1,%2,%3}, [%4];"
                 : "=r"(r0), "=r"(r1), "=r"(r2), "=r"(r3) : "r"(addr));
}

// ---------------------------------------------------------------------------
// Generic transpose + tf32-convert: dst[rowOff + n][k] = tf32(src[k][n]).
// src is [2048][srcCols]. grid (srcCols/32, 2048/32), block (32,8).
// ---------------------------------------------------------------------------
__global__ __launch_bounds__(256) void transpose_kn(
    const float* __restrict__ src, uint32_t* __restrict__ dst,
    int srcCols, int rowOff)
{
    __shared__ uint32_t tile[32][33];
    int x = blockIdx.x * 32 + threadIdx.x;      // n in src
    int y = blockIdx.y * 32 + threadIdx.y;      // k in src
#pragma unroll
    for (int j = 0; j < 32; j += 8)
        tile[threadIdx.y + j][threadIdx.x] =
            f2tf32(src[(size_t)(y + j) * srcCols + x]);
    __syncthreads();
    int nx = blockIdx.y * 32 + threadIdx.x;             // k in dst
    int ny = rowOff + blockIdx.x * 32 + threadIdx.y;    // n in dst
#pragma unroll
    for (int j = 0; j < 32; j += 8)
        dst[(size_t)(ny + j) * D_MODEL + nx] = tile[threadIdx.x][threadIdx.y + j];
}

// ---------------------------------------------------------------------------
// TF32 GEMM (ldmatrix), R6 body. C = A @ Bt^T + bias.
// ---------------------------------------------------------------------------
#define GBM 128
#define GBN 128
#define GBK 32
#define ASTR 36
#define BSTR2 36

__global__ __launch_bounds__(256, 2) void tf32_gemm_bias(
    int M, int N, int K,
    const float* __restrict__ A,
    const uint32_t* __restrict__ Bt,
    const float* __restrict__ bias,
    float* __restrict__ C)
{
    __shared__ uint32_t As[GBM * ASTR];
    __shared__ uint32_t Bs[GBN * BSTR2];

    const int tid  = threadIdx.x;
    const int wid  = tid >> 5;
    const int lane = tid & 31;
    const int g    = lane >> 2;
    const int t4   = lane & 3;
    const int wm   = (wid >> 2) * 64;
    const int wn   = (wid & 3) * 32;

    const float*    Ab = A  + (size_t)blockIdx.y * GBM * K;
    const uint32_t* Bb = Bt + (size_t)blockIdx.x * GBN * K;

    const int lrow = tid >> 3;
    const int lcol = (tid & 7) * 4;

    const int a_row = (lane & 7) + ((lane >> 3) & 1) * 8;
    const int a_kh  = ((lane >> 4) & 1) * 4;
    const int b_row = (lane & 7) + ((lane >> 4) & 1) * 8;
    const int b_kh  = ((lane >> 3) & 1) * 4;

    const uint32_t As_b = (uint32_t)__cvta_generic_to_shared(As);
    const uint32_t Bs_b = (uint32_t)__cvta_generic_to_shared(Bs);

    float acc[4][4][4];
#pragma unroll
    for (int mi = 0; mi < 4; mi++)
#pragma unroll
        for (int ni = 0; ni < 4; ni++)
#pragma unroll
            for (int r = 0; r < 4; r++) acc[mi][ni][r] = 0.0f;

    for (int k0 = 0; k0 < K; k0 += GBK) {
#pragma unroll
        for (int i = 0; i < 4; i++) {
            int row = lrow + 32 * i;
            float4 a = *(const float4*)&Ab[(size_t)row * K + k0 + lcol];
            uint4 u = make_uint4(f2tf32(a.x), f2tf32(a.y), f2tf32(a.z), f2tf32(a.w));
            *(uint4*)&As[row * ASTR + lcol] = u;
        }
#pragma unroll
        for (int i = 0; i < 4; i++) {
            int row = lrow + 32 * i;
            uint4 u = *(const uint4*)&Bb[(size_t)row * K + k0 + lcol];
            *(uint4*)&Bs[row * BSTR2 + lcol] = u;
        }
        __syncthreads();

#pragma unroll
        for (int ks = 0; ks < 4; ks++) {
            uint32_t a[4][4];
#pragma unroll
            for (int mi = 0; mi < 4; mi++) {
                uint32_t addr = As_b +
                    ((wm + mi * 16 + a_row) * ASTR + ks * 8 + a_kh) * 4;
                ldsm_x4(a[mi][0], a[mi][1], a[mi][2], a[mi][3], addr);
            }
            uint32_t bf[2][4];
#pragma unroll
            for (int p = 0; p < 2; p++) {
                uint32_t addr = Bs_b +
                    ((wn + p * 16 + b_row) * BSTR2 + ks * 8 + b_kh) * 4;
                ldsm_x4(bf[p][0], bf[p][1], bf[p][2], bf[p][3], addr);
            }
#pragma unroll
            for (int p = 0; p < 2; p++)
#pragma unroll
                for (int hh = 0; hh < 2; hh++) {
                    const int ni = p * 2 + hh;
#pragma unroll
                    for (int mi = 0; mi < 4; mi++)
                        mma_tf32(acc[mi][ni],
                                 a[mi][0], a[mi][1], a[mi][2], a[mi][3],
                                 bf[p][hh * 2], bf[p][hh * 2 + 1]);
                }
        }
        __syncthreads();
    }

    const int rowBase = blockIdx.y * GBM + wm;
    const int colBase = blockIdx.x * GBN + wn;
#pragma unroll
    for (int mi = 0; mi < 4; mi++) {
#pragma unroll
        for (int ni = 0; ni < 4; ni++) {
            const int col = colBase + ni * 8 + 2 * t4;
            const int r0  = rowBase + mi * 16 + g;
            float2 v0, v1;
            v0.x = acc[mi][ni][0] + bias[col];
            v0.y = acc[mi][ni][1] + bias[col + 1];
            v1.x = acc[mi][ni][2] + bias[col];
            v1.y = acc[mi][ni][3] + bias[col + 1];
            *(float2*)&C[(size_t)r0 * N + col]       = v0;
            *(float2*)&C[(size_t)(r0 + 8) * N + col] = v1;
        }
    }
}

// ---------------------------------------------------------------------------
// K/V projection: TF32 MMA, split-K. Bt = (Wk|Wv)^T [256][2048].
// grid (2, NTOK/128, KVSPLIT). Partials (no bias) -> Cp[z][NTOK][256].
// ---------------------------------------------------------------------------
__global__ __launch_bounds__(256, 2) void kv_gemm_splitk(
    const float* __restrict__ A,
    const uint32_t* __restrict__ Bt,
    float* __restrict__ Cp)
{
    __shared__ uint32_t As[GBM * ASTR];
    __shared__ uint32_t Bs[GBN * BSTR2];

    const int tid  = threadIdx.x;
    const int wid  = tid >> 5;
    const int lane = tid & 31;
    const int g    = lane >> 2;
    const int t4   = lane & 3;
    const int wm   = (wid >> 2) * 64;
    const int wn   = (wid & 3) * 32;

    const float*    Ab = A  + (size_t)blockIdx.y * GBM * D_MODEL;
    const uint32_t* Bb = Bt + (size_t)blockIdx.x * GBN * D_MODEL;
    float*          Cb = Cp + (size_t)blockIdx.z * NTOK * KVN;

    const int lrow = tid >> 3;
    const int lcol = (tid & 7) * 4;

    const int a_row = (lane & 7) + ((lane >> 3) & 1) * 8;
    const int a_kh  = ((lane >> 4) & 1) * 4;
    const int b_row = (lane & 7) + ((lane >> 4) & 1) * 8;
    const int b_kh  = ((lane >> 3) & 1) * 4;

    const uint32_t As_b = (uint32_t)__cvta_generic_to_shared(As);
    const uint32_t Bs_b = (uint32_t)__cvta_generic_to_shared(Bs);

    float acc[4][4][4];
#pragma unroll
    for (int mi = 0; mi < 4; mi++)
#pragma unroll
        for (int ni = 0; ni < 4; ni++)
#pragma unroll
            for (int r = 0; r < 4; r++) acc[mi][ni][r] = 0.0f;

    const int kbeg = blockIdx.z * KCHUNK;
    for (int k0 = kbeg; k0 < kbeg + KCHUNK; k0 += GBK) {
#pragma unroll
        for (int i = 0; i < 4; i++) {
            int row = lrow + 32 * i;
            float4 a = *(const float4*)&Ab[(size_t)row * D_MODEL + k0 + lcol];
            uint4 u = make_uint4(f2tf32(a.x), f2tf32(a.y), f2tf32(a.z), f2tf32(a.w));
            *(uint4*)&As[row * ASTR + lcol] = u;
        }
#pragma unroll
        for (int i = 0; i < 4; i++) {
            int row = lrow + 32 * i;
            uint4 u = *(const uint4*)&Bb[(size_t)row * D_MODEL + k0 + lcol];
            *(uint4*)&Bs[row * BSTR2 + lcol] = u;
        }
        __syncthreads();

#pragma unroll
        for (int ks = 0; ks < 4; ks++) {
            uint32_t a[4][4];
#pragma unroll
            for (int mi = 0; mi < 4; mi++) {
                uint32_t addr = As_b +
                    ((wm + mi * 16 + a_row) * ASTR + ks * 8 + a_kh) * 4;
                ldsm_x4(a[mi][0], a[mi][1], a[mi][2], a[mi][3], addr);
            }
            uint32_t bf[2][4];
#pragma unroll
            for (int p = 0; p < 2; p++) {
                uint32_t addr = Bs_b +
                    ((wn + p * 16 + b_row) * BSTR2 + ks * 8 + b_kh) * 4;
                ldsm_x4(bf[p][0], bf[p][1], bf[p][2], bf[p][3], addr);
            }
#pragma unroll
            for (int p = 0; p < 2; p++)
#pragma unroll
                for (int hh = 0; hh < 2; hh++) {
                    const int ni = p * 2 + hh;
#pragma unroll
                    for (int mi = 0; mi < 4; mi++)
                        mma_tf32(acc[mi][ni],
                                 a[mi][0], a[mi][1], a[mi][2], a[mi][3],
                                 bf[p][hh * 2], bf[p][hh * 2 + 1]);
                }
        }
        __syncthreads();
    }

    const int rowBase = blockIdx.y * GBM + wm;
    const int colBase = blockIdx.x * GBN + wn;
#pragma unroll
    for (int mi = 0; mi < 4; mi++) {
#pragma unroll
        for (int ni = 0; ni < 4; ni++) {
            const int col = colBase + ni * 8 + 2 * t4;
            const int r0  = rowBase + mi * 16 + g;
            *(float2*)&Cb[(size_t)r0 * KVN + col] =
                make_float2(acc[mi][ni][0], acc[mi][ni][1]);
            *(float2*)&Cb[(size_t)(r0 + 8) * KVN + col] =
                make_float2(acc[mi][ni][2], acc[mi][ni][3]);
        }
    }
}

// ---------------------------------------------------------------------------
// Reduce partials + bias. cols 0..127 -> K[tok][d] (float, coalesced).
// cols 128..255 -> Vt[d][tok] (tf32 bits, transposed via smem tile).
// grid (8, NTOK/32), block (32,8).
// ---------------------------------------------------------------------------
__global__ __launch_bounds__(256) void kv_reduce_t(
    const float* __restrict__ Cp,
    const float* __restrict__ bk, const float* __restrict__ bv,
    float* __restrict__ Kout, uint32_t* __restrict__ Vt)
{
    __shared__ float tile[32][33];
    const int col0 = blockIdx.x * 32;
    const int tok0 = blockIdx.y * 32;
    const int tx = threadIdx.x, ty = threadIdx.y;
    const int col = col0 + tx;
    const bool isK = (col0 < HEAD_DIM);
    const float bias = isK ? bk[col] : bv[col - HEAD_DIM];

#pragma unroll
    for (int j = 0; j < 32; j += 8) {
        const int tok = tok0 + ty + j;
        float s = bias;
#pragma unroll
        for (int z = 0; z < KVSPLIT; z++)
            s += Cp[(size_t)z * NTOK * KVN + (size_t)tok * KVN + col];
        if (isK) Kout[(size_t)tok * HEAD_DIM + col] = s;
        else     tile[ty + j][tx] = s;
    }
    if (!isK) {
        __syncthreads();
#pragma unroll
        for (int j = 0; j < 32; j += 8)
            Vt[(size_t)(col0 - HEAD_DIM + ty + j) * NTOK + tok0 + tx] =
                f2tf32(tile[tx][ty + j]);
    }
}

// ---------------------------------------------------------------------------
// TF32 MMA flash attention: ldmatrix score AND PV paths.
// Vt smem tile: [128 d][68 stride] tf32 bits, tokens k-contiguous.
// ---------------------------------------------------------------------------
#define AQ 128
#define AK 64
#define QP 132
#define KP 132
#define VP2 68

__global__ __launch_bounds__(256) void mqa_attn_tf32(
    const float* __restrict__ Q,
    const float* __restrict__ Kg,
    const uint32_t* __restrict__ Vtg,
    const int* __restrict__ mask,
    float* __restrict__ Og)
{
    extern __shared__ uint32_t sm_u[];
    uint32_t* Qs   = sm_u;                    // AQ x QP
    uint32_t* Ks   = Qs + AQ * QP;            // AK x KP
    uint32_t* Vts  = Ks + AK * KP;            // HEAD_DIM x VP2
    float*   sbias = (float*)(Vts + HEAD_DIM * VP2);   // AK

    const int tid  = threadIdx.x;
    const int wid  = tid >> 5;
    const int lane = tid & 31;
    const int g    = lane >> 2;
    const int t4   = lane & 3;
    const int b  = blockIdx.z, h = blockIdx.y;
    const int q0 = blockIdx.x * AQ;
    const int wrow = wid * 16;

    const int a_row = (lane & 7) + ((lane >> 3) & 1) * 8;
    const int a_kh  = ((lane >> 4) & 1) * 4;
    const int b_row = (lane & 7) + ((lane >> 4) & 1) * 8;
    const int b_kh  = ((lane >> 3) & 1) * 4;
    const uint32_t Qs_b  = (uint32_t)__cvta_generic_to_shared(Qs);
    const uint32_t Ks_b  = (uint32_t)__cvta_generic_to_shared(Ks);
    const uint32_t Vts_b = (uint32_t)__cvta_generic_to_shared(Vts);

    // staging coords: K rows (tokens), Vt rows (d)
    const int kpr = tid >> 5;              // K row base (+8u)
    const int kpc = (tid & 31) << 2;       // K col
    const int vpr = tid >> 4;              // Vt row base (+16u)
    const int vpc = (tid & 15) << 2;       // Vt word col (0..60)

    // Load Q tile
    const float* Qp = Q + ((size_t)(b * SEQ + q0)) * D_MODEL + h * HEAD_DIM;
    for (int i = tid; i < AQ * HEAD_DIM / 4; i += 256) {
        int r = i >> 5, c = (i & 31) << 2;
        float4 qv = *(const float4*)&Qp[(size_t)r * D_MODEL + c];
        uint4 u = make_uint4(f2tf32(qv.x), f2tf32(qv.y), f2tf32(qv.z), f2tf32(qv.w));
        *(uint4*)&Qs[r * QP + c] = u;
    }

    // Prefetch tile 0
    float4 kreg[8];
    uint4  vreg[8];
    {
        const float* Kp = Kg + ((size_t)(b * SEQ)) * HEAD_DIM;
#pragma unroll
        for (int u = 0; u < 8; u++) {
            kreg[u] = *(const float4*)&Kp[(size_t)(kpr + 8 * u) * HEAD_DIM + kpc];
            vreg[u] = *(const uint4*)&Vtg[(size_t)(vpr + 16 * u) * NTOK
                                          + b * SEQ + vpc];
        }
    }

    float m0 = -1e30f, m1 = -1e30f, l0 = 0.0f, l1 = 0.0f;
    float o[16][4];
#pragma unroll
    for (int n = 0; n < 16; n++)
#pragma unroll
        for (int r = 0; r < 4; r++) o[n][r] = 0.0f;

    const float scale = 0.08838834764831845f;

    for (int k0 = 0; k0 < SEQ; k0 += AK) {
        __syncthreads();
#pragma unroll
        for (int u = 0; u < 8; u++) {
            const int kr = kpr + 8 * u;
            uint4 ku = make_uint4(f2tf32(kreg[u].x), f2tf32(kreg[u].y),
                                  f2tf32(kreg[u].z), f2tf32(kreg[u].w));
            *(uint4*)&Ks[kr * KP + kpc] = ku;
            *(uint4*)&Vts[(vpr + 16 * u) * VP2 + vpc] = vreg[u];
        }
        if (tid < AK)
            sbias[tid] = mask[(size_t)b * SEQ + k0 + tid] ? 0.0f : -1e9f;
        __syncthreads();

        if (k0 + AK < SEQ) {
            const float* Kp = Kg + ((size_t)(b * SEQ + k0 + AK)) * HEAD_DIM;
#pragma unroll
            for (int u = 0; u < 8; u++) {
                kreg[u] = *(const float4*)&Kp[(size_t)(kpr + 8 * u) * HEAD_DIM + kpc];
                vreg[u] = *(const uint4*)&Vtg[(size_t)(vpr + 16 * u) * NTOK
                                              + b * SEQ + k0 + AK + vpc];
            }
        }

        // ---- Scores ----
        float s[8][4];
#pragma unroll
        for (int j = 0; j < 8; j++)
#pragma unroll
            for (int r = 0; r < 4; r++) s[j][r] = 0.0f;

#pragma unroll
        for (int ks = 0; ks < 16; ks++) {
            uint32_t aq[4];
            ldsm_x4(aq[0], aq[1], aq[2], aq[3],
                    Qs_b + ((wrow + a_row) * QP + ks * 8 + a_kh) * 4);
#pragma unroll
            for (int p = 0; p < 4; p++) {
                uint32_t bf[4];
                ldsm_x4(bf[0], bf[1], bf[2], bf[3],
                        Ks_b + ((p * 16 + b_row) * KP + ks * 8 + b_kh) * 4);
                mma_tf32(s[2 * p],     aq[0], aq[1], aq[2], aq[3], bf[0], bf[1]);
                mma_tf32(s[2 * p + 1], aq[0], aq[1], aq[2], aq[3], bf[2], bf[3]);
            }
        }

        // ---- scale + mask, softmax ----
        float rmax0 = -1e30f, rmax1 = -1e30f;
#pragma unroll
        for (int j = 0; j < 8; j++) {
            float2 sb = *(float2*)&sbias[j * 8 + 2 * t4];
            s[j][0] = s[j][0] * scale + sb.x;
            s[j][1] = s[j][1] * scale + sb.y;
            s[j][2] = s[j][2] * scale + sb.x;
            s[j][3] = s[j][3] * scale + sb.y;
            rmax0 = fmaxf(rmax0, fmaxf(s[j][0], s[j][1]));
            rmax1 = fmaxf(rmax1, fmaxf(s[j][2], s[j][3]));
        }
#pragma unroll
        for (int off = 1; off <= 2; off <<= 1) {
            rmax0 = fmaxf(rmax0, __shfl_xor_sync(0xffffffffu, rmax0, off));
            rmax1 = fmaxf(rmax1, __shfl_xor_sync(0xffffffffu, rmax1, off));
        }
        const float mn0 = fmaxf(m0, rmax0);
        const float mn1 = fmaxf(m1, rmax1);
        const float c0 = __expf(m0 - mn0);
        const float c1 = __expf(m1 - mn1);
        m0 = mn0; m1 = mn1;

        float rs0 = 0.0f, rs1 = 0.0f;
        uint32_t pt[8][4];
#pragma unroll
        for (int j = 0; j < 8; j++) {
            float p0 = __expf(s[j][0] - mn0);
            float p1 = __expf(s[j][1] - mn0);
            float p2 = __expf(s[j][2] - mn1);
            float p3 = __expf(s[j][3] - mn1);
            rs0 += p0 + p1;
            rs1 += p2 + p3;
            pt[j][0] = f2tf32(p0);
            pt[j][1] = f2tf32(p1);
            pt[j][2] = f2tf32(p2);
            pt[j][3] = f2tf32(p3);
        }
#pragma unroll
        for (int off = 1; off <= 2; off <<= 1) {
            rs0 += __shfl_xor_sync(0xffffffffu, rs0, off);
            rs1 += __shfl_xor_sync(0xffffffffu, rs1, off);
        }
        l0 = l0 * c0 + rs0;
        l1 = l1 * c1 + rs1;

#pragma unroll
        for (int n = 0; n < 16; n++) {
            o[n][0] *= c0; o[n][1] *= c0;
            o[n][2] *= c1; o[n][3] *= c1;
        }

        // ---- O += P @ V (ldmatrix on Vt) ----
        const int src1 = (g << 2) + (t4 >> 1);
        const int src2 = src1 + 2;
        const bool odd = (t4 & 1);
#pragma unroll
        for (int j = 0; j < 8; j++) {
            uint32_t x00 = __shfl_sync(0xffffffffu, pt[j][0], src1);
            uint32_t x01 = __shfl_sync(0xffffffffu, pt[j][1], src1);
            uint32_t x10 = __shfl_sync(0xffffffffu, pt[j][0], src2);
            uint32_t x11 = __shfl_sync(0xffffffffu, pt[j][1], src2);
            uint32_t x20 = __shfl_sync(0xffffffffu, pt[j][2], src1);
            uint32_t x21 = __shfl_sync(0xffffffffu, pt[j][3], src1);
            uint32_t x30 = __shfl_sync(0xffffffffu, pt[j][2], src2);
            uint32_t x31 = __shfl_sync(0xffffffffu, pt[j][3], src2);
            uint32_t a0 = odd ? x01 : x00;
            uint32_t a2 = odd ? x11 : x10;
            uint32_t a1 = odd ? x21 : x20;
            uint32_t a3 = odd ? x31 : x30;
#pragma unroll
            for (int p = 0; p < 8; p++) {
                uint32_t bf[4];
                ldsm_x4(bf[0], bf[1], bf[2], bf[3],
                        Vts_b + ((p * 16 + b_row) * VP2 + j * 8 + b_kh) * 4);
                mma_tf32(o[2 * p],     a0, a1, a2, a3, bf[0], bf[1]);
                mma_tf32(o[2 * p + 1], a0, a1, a2, a3, bf[2], bf[3]);
            }
        }
    }

    // ---- Epilogue ----
    const float inv0 = 1.0f / l0;
    const float inv1 = 1.0f / l1;
    float* Op0 = Og + ((size_t)(b * SEQ + q0 + wrow + g    )) * D_MODEL + h * HEAD_DIM;
    float* Op1 = Og + ((size_t)(b * SEQ + q0 + wrow + g + 8)) * D_MODEL + h * HEAD_DIM;
#pragma unroll
    for (int n = 0; n < 16; n++) {
        const int col = n * 8 + 2 * t4;
        float2 v0, v1;
        v0.x = o[n][0] * inv0; v0.y = o[n][1] * inv0;
        v1.x = o[n][2] * inv1; v1.y = o[n][3] * inv1;
        *(float2*)&Op0[col] = v0;
        *(float2*)&Op1[col] = v1;
    }
}

// ---------------------------------------------------------------------------
extern "C" void kernel_launch(void* const* d_in, const int* in_sizes, int n_in,
                              void* d_out, int out_size)
{
    const float* x    = (const float*)d_in[0];
    const int*   mask = (const int*)d_in[1];
    const float* Wq   = (const float*)d_in[2];
    const float* bq   = (const float*)d_in[3];
    const float* Wk   = (const float*)d_in[4];
    const float* bk   = (const float*)d_in[5];
    const float* Wv   = (const float*)d_in[6];
    const float* bv   = (const float*)d_in[7];
    const float* Wo   = (const float*)d_in[8];
    const float* bo   = (const float*)d_in[9];
    float* out = (float*)d_out;

    float *q, *k, *ao, *kvp;
    uint32_t *vt, *wqt, *wot, *wkvt;
    cudaGetSymbolAddress((void**)&q,    g_q);
    cudaGetSymbolAddress((void**)&k,    g_k);
    cudaGetSymbolAddress((void**)&vt,   g_vt);
    cudaGetSymbolAddress((void**)&ao,   g_ao);
    cudaGetSymbolAddress((void**)&kvp,  g_kvp);
    cudaGetSymbolAddress((void**)&wqt,  g_wqt);
    cudaGetSymbolAddress((void**)&wot,  g_wot);
    cudaGetSymbolAddress((void**)&wkvt, g_wkvt);

    // Weight transposes (tf32)
    transpose_kn<<<dim3(64, 64), dim3(32, 8)>>>(Wq, wqt, D_MODEL, 0);
    transpose_kn<<<dim3(64, 64), dim3(32, 8)>>>(Wo, wot, D_MODEL, 0);
    transpose_kn<<<dim3(4, 64),  dim3(32, 8)>>>(Wk, wkvt, HEAD_DIM, 0);
    transpose_kn<<<dim3(4, 64),  dim3(32, 8)>>>(Wv, wkvt, HEAD_DIM, HEAD_DIM);

    // Q projection
    tf32_gemm_bias<<<dim3(D_MODEL / GBN, NTOK / GBM), 256>>>(
        NTOK, D_MODEL, D_MODEL, x, wqt, bq, q);

    // K/V projection: tf32 split-K MMA + reduce (K normal, V transposed tf32)
    kv_gemm_splitk<<<dim3(KVN / GBN, NTOK / GBM, KVSPLIT), 256>>>(x, wkvt, kvp);
    kv_reduce_t<<<dim3(KVN / 32, NTOK / 32), dim3(32, 8)>>>(kvp, bk, bv, k, vt);

    // Attention
    size_t smem = (size_t)(AQ * QP + AK * KP + HEAD_DIM * VP2) * 4
                + AK * sizeof(float);
    cudaFuncSetAttribute(mqa_attn_tf32,
                         cudaFuncAttributeMaxDynamicSharedMemorySize, (int)smem);
    mqa_attn_tf32<<<dim3(SEQ / AQ, N_HEADS, BATCH), 256, smem>>>(q, k, vt, mask, ao);

    // Output projection
    tf32_gemm_bias<<<dim3(D_MODEL / GBN, NTOK / GBM), 256>>>(
        NTOK, D_MODEL, D_MODEL, ao, wot, bo, out);
}